// round 2
// baseline (speedup 1.0000x reference)
#include <cuda_runtime.h>
#include <cuda_bf16.h>
#include <math.h>

// Problem constants
#define G 256
#define N0 256
#define HF 256            // hidden feature dim
#define MAXN (G*N0)       // 65536
#define MAXE (G*2048)     // 524288

// -------- scratch (device globals; no allocation allowed) --------
__device__ float g_h[MAXN*HF];        // 64 MB : h = x @ W
__device__ float g_agg[MAXN*HF];      // 64 MB : agg, then conv output
__device__ float g_x[(MAXN/2)*HF];    // 32 MB : pooled features
__device__ float g_deg[MAXN];
__device__ float g_score[MAXN];
__device__ int   g_newid[MAXN];
__device__ int   g_perm[MAXN/2];
__device__ int   g_esrc0[MAXE], g_edst0[MAXE];
__device__ float g_eew0[MAXE];
__device__ int   g_esrc1[MAXE], g_edst1[MAXE];
__device__ float g_eew1[MAXE];
__device__ float g_ro[G*512];
__device__ float g_h1[G*256];
__device__ float g_h2[G*128];
__device__ float g_winv;

// ---------------- GEMM: C[n,256] = X[n,K] @ W[K,256] ----------------
#define BM 64
#define BN 64
#define BK 16
__global__ void gemm_kernel(const float* __restrict__ X, const float* __restrict__ W,
                            float* __restrict__ C, int n, int K) {
    __shared__ float As[BK][BM];
    __shared__ float Bs[BK][BN];
    int tid = threadIdx.x;
    int tr = tid >> 4, tc = tid & 15;
    int rowBase = blockIdx.x * BM;
    int colBase = blockIdx.y * BN;
    float acc[4][4];
    #pragma unroll
    for (int i = 0; i < 4; i++)
        #pragma unroll
        for (int j = 0; j < 4; j++) acc[i][j] = 0.f;

    for (int k0 = 0; k0 < K; k0 += BK) {
        #pragma unroll
        for (int i = tid; i < BM*BK; i += 256) {
            int r = i >> 4, c = i & 15;
            As[c][r] = X[(size_t)(rowBase + r) * K + k0 + c];
        }
        #pragma unroll
        for (int i = tid; i < BK*BN; i += 256) {
            int r = i >> 6, c = i & 63;
            Bs[r][c] = W[(size_t)(k0 + r) * 256 + colBase + c];
        }
        __syncthreads();
        #pragma unroll
        for (int kk = 0; kk < BK; kk++) {
            float a[4], b[4];
            #pragma unroll
            for (int i = 0; i < 4; i++) a[i] = As[kk][tr*4+i];
            #pragma unroll
            for (int j = 0; j < 4; j++) b[j] = Bs[kk][tc*4+j];
            #pragma unroll
            for (int i = 0; i < 4; i++)
                #pragma unroll
                for (int j = 0; j < 4; j++) acc[i][j] += a[i] * b[j];
        }
        __syncthreads();
    }
    #pragma unroll
    for (int i = 0; i < 4; i++)
        #pragma unroll
        for (int j = 0; j < 4; j++)
            C[(size_t)(rowBase + tr*4 + i) * 256 + colBase + tc*4 + j] = acc[i][j];
}

// ---------------- degree ----------------
__global__ void deg_init_kernel(float* deg, int n) {
    int i = blockIdx.x * blockDim.x + threadIdx.x;
    if (i < n) deg[i] = 1.0f;
}
__global__ void deg_edge_kernel(const int* __restrict__ dst, const float* __restrict__ ew,
                                float* deg, int E) {
    int e = blockIdx.x * blockDim.x + threadIdx.x;
    if (e >= E) return;
    float w = ew ? ew[e] : 1.0f;
    if (w != 0.f) atomicAdd(&deg[dst[e]], w);
}

// ---------------- zero fill ----------------
__global__ void zero_kernel(float4* p, int n4) {
    int i = blockIdx.x * blockDim.x + threadIdx.x;
    if (i < n4) p[i] = make_float4(0.f, 0.f, 0.f, 0.f);
}

// ---------------- edge aggregation (warp per edge) ----------------
__global__ void agg_edge_kernel(const int* __restrict__ src, const int* __restrict__ dst,
                                const float* __restrict__ ew, const float* __restrict__ deg,
                                const float* __restrict__ h, float* __restrict__ out, int E) {
    int gt = blockIdx.x * blockDim.x + threadIdx.x;
    int e = gt >> 5, lane = gt & 31;
    if (e >= E) return;
    float w = ew ? ew[e] : 1.0f;
    if (w == 0.f) return;
    int s = src[e], d = dst[e];
    float norm = rsqrtf(deg[s]) * rsqrtf(deg[d]) * w;
    const float4* hs = (const float4*)(h + (size_t)s * HF);
    float4* od = (float4*)(out + (size_t)d * HF);
    #pragma unroll
    for (int f = lane; f < HF/4; f += 32) {
        float4 v = hs[f];
        v.x *= norm; v.y *= norm; v.z *= norm; v.w *= norm;
#if __CUDA_ARCH__ >= 900
        atomicAdd(od + f, v);
#else
        atomicAdd(&((float*)od)[f*4+0], v.x);
        atomicAdd(&((float*)od)[f*4+1], v.y);
        atomicAdd(&((float*)od)[f*4+2], v.z);
        atomicAdd(&((float*)od)[f*4+3], v.w);
#endif
    }
}

// ---------------- combine: out = relu(agg + h/deg + b) ----------------
__global__ void combine_kernel(const float* __restrict__ h, const float* __restrict__ deg,
                               const float* __restrict__ b, float* __restrict__ out, int n) {
    int i = blockIdx.x * blockDim.x + threadIdx.x;
    if (i >= n * HF) return;
    int node = i >> 8, f = i & 255;
    float v = out[i] + h[i] / deg[node] + b[f];
    out[i] = fmaxf(v, 0.f);
}

// ---------------- pooling ----------------
__global__ void wnorm_kernel(const float* __restrict__ w) {
    __shared__ float red[256];
    int t = threadIdx.x;
    float v = w[t];
    red[t] = v * v;
    __syncthreads();
    for (int s = 128; s > 0; s >>= 1) {
        if (t < s) red[t] += red[t + s];
        __syncthreads();
    }
    if (t == 0) g_winv = rsqrtf(red[0]);
}

__global__ void score_kernel(const float* __restrict__ x, const float* __restrict__ w,
                             float* __restrict__ score, int n) {
    int gt = blockIdx.x * blockDim.x + threadIdx.x;
    int node = gt >> 5, lane = gt & 31;
    if (node >= n) return;
    const float* row = x + (size_t)node * HF;
    float s = 0.f;
    #pragma unroll
    for (int f = lane; f < HF; f += 32) s += row[f] * w[f];
    #pragma unroll
    for (int o = 16; o > 0; o >>= 1) s += __shfl_down_sync(0xFFFFFFFFu, s, o);
    if (lane == 0) score[node] = tanhf(s * g_winv);
}

// one block per graph; threads = npg; rank-count selection == stable top_k
__global__ void pool_kernel(const float* __restrict__ score, int npg, int k,
                            int* __restrict__ newid, int* __restrict__ perm) {
    __shared__ float s[256];
    int g = blockIdx.x, t = threadIdx.x;
    int node = g * npg + t;
    float my = score[node];
    s[t] = my;
    __syncthreads();
    int rank = 0;
    for (int j = 0; j < npg; j++) {
        float v = s[j];
        rank += (v > my) || (v == my && j < t);
    }
    if (rank < k) {
        newid[node] = g * k + rank;
        perm[g * k + rank] = node;
    } else {
        newid[node] = -1;
    }
}

__global__ void gather_scale_kernel(const float* __restrict__ x, const float* __restrict__ score,
                                    const int* __restrict__ perm, float* __restrict__ nx, int nNew) {
    int i = blockIdx.x * blockDim.x + threadIdx.x;
    if (i >= nNew * HF) return;
    int nn = i >> 8, f = i & 255;
    int old = perm[nn];
    nx[i] = x[(size_t)old * HF + f] * score[old];
}

__global__ void remap_kernel(const int* __restrict__ src, const int* __restrict__ dst,
                             const float* __restrict__ ew, const int* __restrict__ newid,
                             int* __restrict__ nsrc, int* __restrict__ ndst,
                             float* __restrict__ new_ew, int E) {
    int e = blockIdx.x * blockDim.x + threadIdx.x;
    if (e >= E) return;
    int s = newid[src[e]], d = newid[dst[e]];
    float w = ew ? ew[e] : 1.0f;
    bool valid = (s >= 0) && (d >= 0);
    nsrc[e]   = valid ? s : 0;
    ndst[e]   = valid ? d : 0;
    new_ew[e] = valid ? w : 0.f;
}

// ---------------- readout: [max | mean] per graph ----------------
__global__ void readout_kernel(const float* __restrict__ x, int k,
                               float* __restrict__ ro, int accumulate) {
    int g = blockIdx.x, f = threadIdx.x;  // 256 threads
    const float* base = x + (size_t)g * k * HF + f;
    float mx = -3.4e38f, sum = 0.f;
    for (int j = 0; j < k; j++) {
        float v = base[(size_t)j * HF];
        mx = fmaxf(mx, v);
        sum += v;
    }
    float mean = sum / (float)k;
    if (accumulate) {
        ro[g*512 + f]       += mx;
        ro[g*512 + 256 + f] += mean;
    } else {
        ro[g*512 + f]       = mx;
        ro[g*512 + 256 + f] = mean;
    }
}

// ---------------- MLP ----------------
__global__ void lin1_kernel(const float* __restrict__ in, const float* __restrict__ W,
                            const float* __restrict__ b, float* __restrict__ out) {
    int g = blockIdx.x, c = threadIdx.x;  // 256 threads
    __shared__ float row[512];
    for (int i = c; i < 512; i += 256) row[i] = in[g*512 + i];
    __syncthreads();
    float acc = b[c];
    #pragma unroll 8
    for (int kk = 0; kk < 512; kk++) acc += row[kk] * W[kk*256 + c];
    out[g*256 + c] = fmaxf(acc, 0.f);
}
__global__ void lin2_kernel(const float* __restrict__ in, const float* __restrict__ W,
                            const float* __restrict__ b, float* __restrict__ out) {
    int g = blockIdx.x, c = threadIdx.x;  // 128 threads
    __shared__ float row[256];
    for (int i = c; i < 256; i += 128) row[i] = in[g*256 + i];
    __syncthreads();
    float acc = b[c];
    #pragma unroll 8
    for (int kk = 0; kk < 256; kk++) acc += row[kk] * W[kk*128 + c];
    out[g*128 + c] = fmaxf(acc, 0.f);
}
__global__ void lin3_lsm_kernel(const float* __restrict__ in, const float* __restrict__ W,
                                const float* __restrict__ b, float* __restrict__ out) {
    int g = blockIdx.x, lane = threadIdx.x;  // 32 threads
    const float* row = in + g*128;
    float a0 = 0.f, a1 = 0.f;
    #pragma unroll
    for (int kk = lane; kk < 128; kk += 32) {
        float v = row[kk];
        a0 += v * W[kk*2 + 0];
        a1 += v * W[kk*2 + 1];
    }
    #pragma unroll
    for (int o = 16; o > 0; o >>= 1) {
        a0 += __shfl_down_sync(0xFFFFFFFFu, a0, o);
        a1 += __shfl_down_sync(0xFFFFFFFFu, a1, o);
    }
    if (lane == 0) {
        float l0 = a0 + b[0], l1 = a1 + b[1];
        float m = fmaxf(l0, l1);
        float lse = m + logf(expf(l0 - m) + expf(l1 - m));
        out[g*2 + 0] = l0 - lse;
        out[g*2 + 1] = l1 - lse;
    }
}

// ---------------- host driver ----------------
static void run_conv(const float* x, int n, int K, const float* Wg, const float* bg,
                     const int* esrc, const int* edst, const float* eew, int E,
                     float* p_h, float* p_agg, float* p_deg) {
    dim3 ggrid(n / BM, 256 / BN);
    gemm_kernel<<<ggrid, 256>>>(x, Wg, p_h, n, K);
    deg_init_kernel<<<(n + 255) / 256, 256>>>(p_deg, n);
    deg_edge_kernel<<<(E + 255) / 256, 256>>>(edst, eew, p_deg, E);
    zero_kernel<<<((n * HF / 4) + 255) / 256, 256>>>((float4*)p_agg, n * HF / 4);
    agg_edge_kernel<<<(E * 32 + 255) / 256, 256>>>(esrc, edst, eew, p_deg, p_h, p_agg, E);
    combine_kernel<<<(n * HF + 255) / 256, 256>>>(p_h, p_deg, bg, p_agg, n);
}

extern "C" void kernel_launch(void* const* d_in, const int* in_sizes, int n_in,
                              void* d_out, int out_size) {
    const float* d_x      = (const float*)d_in[0];
    const int*   d_ei     = (const int*)d_in[1];
    const float* gcn_w0   = (const float*)d_in[3];
    const float* gcn_b0   = (const float*)d_in[4];
    const float* gcn_w1   = (const float*)d_in[5];
    const float* gcn_b1   = (const float*)d_in[6];
    const float* gcn_w2   = (const float*)d_in[7];
    const float* gcn_b2   = (const float*)d_in[8];
    const float* pool_w0  = (const float*)d_in[9];
    const float* pool_w1  = (const float*)d_in[10];
    const float* pool_w2  = (const float*)d_in[11];
    const float* lin1_w   = (const float*)d_in[12];
    const float* lin1_b   = (const float*)d_in[13];
    const float* lin2_w   = (const float*)d_in[14];
    const float* lin2_b   = (const float*)d_in[15];
    const float* lin3_w   = (const float*)d_in[16];
    const float* lin3_b   = (const float*)d_in[17];
    float* out = (float*)d_out;

    const int E = in_sizes[1] / 2;
    const int* d_src = d_ei;
    const int* d_dst = d_ei + E;

    float *p_h, *p_agg, *p_x, *p_deg, *p_score, *p_ro, *p_h1, *p_h2;
    int *p_newid, *p_perm, *p_es0, *p_ed0, *p_es1, *p_ed1;
    float *p_ew0, *p_ew1;
    cudaGetSymbolAddress((void**)&p_h,    g_h);
    cudaGetSymbolAddress((void**)&p_agg,  g_agg);
    cudaGetSymbolAddress((void**)&p_x,    g_x);
    cudaGetSymbolAddress((void**)&p_deg,  g_deg);
    cudaGetSymbolAddress((void**)&p_score,g_score);
    cudaGetSymbolAddress((void**)&p_newid,g_newid);
    cudaGetSymbolAddress((void**)&p_perm, g_perm);
    cudaGetSymbolAddress((void**)&p_es0,  g_esrc0);
    cudaGetSymbolAddress((void**)&p_ed0,  g_edst0);
    cudaGetSymbolAddress((void**)&p_ew0,  g_eew0);
    cudaGetSymbolAddress((void**)&p_es1,  g_esrc1);
    cudaGetSymbolAddress((void**)&p_ed1,  g_edst1);
    cudaGetSymbolAddress((void**)&p_ew1,  g_eew1);
    cudaGetSymbolAddress((void**)&p_ro,   g_ro);
    cudaGetSymbolAddress((void**)&p_h1,   g_h1);
    cudaGetSymbolAddress((void**)&p_h2,   g_h2);

    // ---------------- level 0 ----------------
    int n = MAXN;                 // 65536 nodes
    run_conv(d_x, n, 128, gcn_w0, gcn_b0, d_src, d_dst, nullptr, E, p_h, p_agg, p_deg);

    // pool 0: npg=256 -> k=128
    {
        int npg = 256, k = 128, nNew = G * k;
        wnorm_kernel<<<1, 256>>>(pool_w0);
        score_kernel<<<(n * 32 + 255) / 256, 256>>>(p_agg, pool_w0, p_score, n);
        pool_kernel<<<G, npg>>>(p_score, npg, k, p_newid, p_perm);
        gather_scale_kernel<<<(nNew * HF + 255) / 256, 256>>>(p_agg, p_score, p_perm, p_x, nNew);
        remap_kernel<<<(E + 255) / 256, 256>>>(d_src, d_dst, nullptr, p_newid,
                                               p_es0, p_ed0, p_ew0, E);
        readout_kernel<<<G, 256>>>(p_x, k, p_ro, 0);
        n = nNew;                 // 32768
    }

    // ---------------- level 1 ----------------
    run_conv(p_x, n, 256, gcn_w1, gcn_b1, p_es0, p_ed0, p_ew0, E, p_h, p_agg, p_deg);
    {
        int npg = 128, k = 64, nNew = G * k;
        wnorm_kernel<<<1, 256>>>(pool_w1);
        score_kernel<<<(n * 32 + 255) / 256, 256>>>(p_agg, pool_w1, p_score, n);
        pool_kernel<<<G, npg>>>(p_score, npg, k, p_newid, p_perm);
        gather_scale_kernel<<<(nNew * HF + 255) / 256, 256>>>(p_agg, p_score, p_perm, p_x, nNew);
        remap_kernel<<<(E + 255) / 256, 256>>>(p_es0, p_ed0, p_ew0, p_newid,
                                               p_es1, p_ed1, p_ew1, E);
        readout_kernel<<<G, 256>>>(p_x, k, p_ro, 1);
        n = nNew;                 // 16384
    }

    // ---------------- level 2 ----------------
    run_conv(p_x, n, 256, gcn_w2, gcn_b2, p_es1, p_ed1, p_ew1, E, p_h, p_agg, p_deg);
    {
        int npg = 64, k = 32, nNew = G * k;
        wnorm_kernel<<<1, 256>>>(pool_w2);
        score_kernel<<<(n * 32 + 255) / 256, 256>>>(p_agg, pool_w2, p_score, n);
        pool_kernel<<<G, npg>>>(p_score, npg, k, p_newid, p_perm);
        gather_scale_kernel<<<(nNew * HF + 255) / 256, 256>>>(p_agg, p_score, p_perm, p_x, nNew);
        // no remap needed: no further conv
        readout_kernel<<<G, 256>>>(p_x, k, p_ro, 1);
    }

    // ---------------- MLP head ----------------
    lin1_kernel<<<G, 256>>>(p_ro, lin1_w, lin1_b, p_h1);
    lin2_kernel<<<G, 128>>>(p_h1, lin2_w, lin2_b, p_h2);
    lin3_lsm_kernel<<<G, 32>>>(p_h2, lin3_w, lin3_b, out);
}

// round 3
// speedup vs baseline: 1.4917x; 1.4917x over previous
#include <cuda_runtime.h>
#include <cuda_bf16.h>
#include <math.h>

// Problem constants
#define G 256
#define N0 256
#define HF 256            // hidden feature dim
#define MAXN (G*N0)       // 65536
#define MAXE (G*2048)     // 524288
#define EPG 2048          // edges per graph (fixed slot count, masked edges have ew=0)

// -------- scratch (device globals; no allocation allowed) --------
__device__ float g_h[MAXN*HF];        // 64 MB : h = x @ W
__device__ float g_agg[MAXN*HF];      // 64 MB : conv output
__device__ float g_x[(MAXN/2)*HF];    // 32 MB : pooled features
__device__ float g_dinv[MAXN];
__device__ float g_score[MAXN];
__device__ int   g_newid[MAXN];
__device__ int   g_perm[MAXN/2];
__device__ int   g_esrc0[MAXE], g_edst0[MAXE];
__device__ float g_eew0[MAXE];
__device__ int   g_esrc1[MAXE], g_edst1[MAXE];
__device__ float g_eew1[MAXE];
__device__ int   g_rs[MAXN];          // CSR row start (per-graph relative)
__device__ int   g_rc[MAXN];          // CSR row count
__device__ int   g_csrc[MAXE];        // CSR src (graph-local)
__device__ float g_cnorm[MAXE];       // CSR edge norm
__device__ float g_ro[G*512];
__device__ float g_h1[G*256];
__device__ float g_h2[G*128];
__device__ float g_winv;

// ---------------- GEMM: C[n,256] = X[n,K] @ W[K,256] ----------------
// 128x128 tile, 8x8 per thread, 256 threads
#define GBM 128
#define GBN 128
#define GBK 16
__global__ __launch_bounds__(256) void gemm_kernel(
        const float* __restrict__ X, const float* __restrict__ W,
        float* __restrict__ C, int n, int K) {
    __shared__ float As[GBK][GBM];
    __shared__ float Bs[GBK][GBN];
    int tid = threadIdx.x;
    int rowBase = blockIdx.x * GBM;
    int colBase = blockIdx.y * GBN;
    int tr = tid >> 4, tc = tid & 15;       // 16 x 16 thread grid

    float acc[8][8];
    #pragma unroll
    for (int i = 0; i < 8; i++)
        #pragma unroll
        for (int j = 0; j < 8; j++) acc[i][j] = 0.f;

    for (int k0 = 0; k0 < K; k0 += GBK) {
        // A tile: 128 rows x 16 k = 512 float4 (2 per thread), store transposed
        #pragma unroll
        for (int l = 0; l < 2; l++) {
            int idx = tid * 2 + l;          // 0..511
            int r = idx >> 2, q = idx & 3;  // row 0..127, k-quad 0..3
            float4 v = *(const float4*)(X + (size_t)(rowBase + r) * K + k0 + q * 4);
            As[q*4+0][r] = v.x; As[q*4+1][r] = v.y;
            As[q*4+2][r] = v.z; As[q*4+3][r] = v.w;
        }
        // B tile: 16 k x 128 cols = 512 float4 (2 per thread), natural layout
        #pragma unroll
        for (int l = 0; l < 2; l++) {
            int idx = tid * 2 + l;
            int r = idx >> 5, c = idx & 31; // k 0..15, col-quad 0..31
            *(float4*)&Bs[r][c*4] =
                *(const float4*)(W + (size_t)(k0 + r) * 256 + colBase + c * 4);
        }
        __syncthreads();
        #pragma unroll
        for (int kk = 0; kk < GBK; kk++) {
            float a[8], b[8];
            *(float4*)&a[0] = *(float4*)&As[kk][tr*8];
            *(float4*)&a[4] = *(float4*)&As[kk][tr*8+4];
            *(float4*)&b[0] = *(float4*)&Bs[kk][tc*8];
            *(float4*)&b[4] = *(float4*)&Bs[kk][tc*8+4];
            #pragma unroll
            for (int i = 0; i < 8; i++)
                #pragma unroll
                for (int j = 0; j < 8; j++) acc[i][j] += a[i] * b[j];
        }
        __syncthreads();
    }
    #pragma unroll
    for (int i = 0; i < 8; i++) {
        float* crow = C + (size_t)(rowBase + tr*8 + i) * 256 + colBase + tc*8;
        *(float4*)crow       = make_float4(acc[i][0], acc[i][1], acc[i][2], acc[i][3]);
        *(float4*)(crow + 4) = make_float4(acc[i][4], acc[i][5], acc[i][6], acc[i][7]);
    }
}

// ---------------- per-graph CSR build (block = graph, 256 threads) ----------------
__global__ __launch_bounds__(256) void csr_build_kernel(
        const int* __restrict__ src, const int* __restrict__ dst,
        const float* __restrict__ ew, int npg,
        int* __restrict__ rs, int* __restrict__ rc,
        int* __restrict__ csrc, float* __restrict__ cnorm,
        float* __restrict__ dinv) {
    __shared__ float sdeg[256];
    __shared__ int   scnt[256];
    __shared__ int   sscan[256];
    __shared__ int   spos[256];
    int g = blockIdx.x, t = threadIdx.x;
    int nbase = g * npg, ebase = g * EPG;

    if (t < npg) { sdeg[t] = 1.0f; scnt[t] = 0; }
    __syncthreads();
    for (int e = t; e < EPG; e += 256) {
        float w = ew ? ew[ebase + e] : 1.0f;
        if (w != 0.f) {
            int d = dst[ebase + e] - nbase;
            atomicAdd(&sdeg[d], w);
            atomicAdd(&scnt[d], 1);
        }
    }
    __syncthreads();
    // inclusive scan of counts -> exclusive starts
    int v = (t < npg) ? scnt[t] : 0;
    sscan[t] = v;
    __syncthreads();
    #pragma unroll
    for (int off = 1; off < 256; off <<= 1) {
        int add = (t >= off) ? sscan[t - off] : 0;
        __syncthreads();
        sscan[t] += add;
        __syncthreads();
    }
    int start = sscan[t] - v;
    if (t < npg) {
        rs[nbase + t] = start;
        rc[nbase + t] = v;
        spos[t] = start;
        dinv[nbase + t] = 1.0f / sdeg[t];
    }
    __syncthreads();
    for (int e = t; e < EPG; e += 256) {
        float w = ew ? ew[ebase + e] : 1.0f;
        if (w != 0.f) {
            int s = src[ebase + e] - nbase;
            int d = dst[ebase + e] - nbase;
            float nm = rsqrtf(sdeg[s]) * rsqrtf(sdeg[d]) * w;
            int idx = atomicAdd(&spos[d], 1);
            csrc[ebase + idx]  = s;
            cnorm[ebase + idx] = nm;
        }
    }
}

// ---------------- fused aggregation + self-loop + bias + relu ----------------
// block = (feat-chunk fc in [0,4), graph g); stages h tile [npg][64] in smem
__global__ __launch_bounds__(256) void agg_fused_kernel(
        const float* __restrict__ h, const float* __restrict__ dinv,
        const int* __restrict__ rs, const int* __restrict__ rc,
        const int* __restrict__ csrc, const float* __restrict__ cnorm,
        const float* __restrict__ bias, float* __restrict__ out, int npg) {
    extern __shared__ float ht[];   // npg * 64 floats
    int fc = blockIdx.x, g = blockIdx.y;
    int t = threadIdx.x;
    int nbase = g * npg, ebase = g * EPG;

    const float4* h4 = (const float4*)h;
    float4* ht4 = (float4*)ht;
    for (int i = t; i < npg * 16; i += 256) {
        int node = i >> 4, q = i & 15;
        ht4[i] = h4[(size_t)(nbase + node) * 64 + fc * 16 + q];
    }
    __syncthreads();

    int w = t >> 5, lane = t & 31;
    float b0 = __ldg(bias + fc*64 + lane*2);
    float b1 = __ldg(bias + fc*64 + lane*2 + 1);
    for (int d = w; d < npg; d += 8) {
        float dv = dinv[nbase + d];
        float a0 = ht[d*64 + lane*2]     * dv + b0;
        float a1 = ht[d*64 + lane*2 + 1] * dv + b1;
        int cnt = rc[nbase + d], st = rs[nbase + d];
        const int*   cs = csrc  + ebase + st;
        const float* cn = cnorm + ebase + st;
        for (int e = 0; e < cnt; e++) {
            int s   = cs[e];
            float nm = cn[e];
            a0 += nm * ht[s*64 + lane*2];
            a1 += nm * ht[s*64 + lane*2 + 1];
        }
        float2 o;
        o.x = fmaxf(a0, 0.f);
        o.y = fmaxf(a1, 0.f);
        *(float2*)(out + (size_t)(nbase + d) * 256 + fc*64 + lane*2) = o;
    }
}

// ---------------- pooling ----------------
__global__ void wnorm_kernel(const float* __restrict__ w) {
    __shared__ float red[256];
    int t = threadIdx.x;
    float v = w[t];
    red[t] = v * v;
    __syncthreads();
    for (int s = 128; s > 0; s >>= 1) {
        if (t < s) red[t] += red[t + s];
        __syncthreads();
    }
    if (t == 0) g_winv = rsqrtf(red[0]);
}

__global__ void score_kernel(const float* __restrict__ x, const float* __restrict__ w,
                             float* __restrict__ score, int n) {
    int gt = blockIdx.x * blockDim.x + threadIdx.x;
    int node = gt >> 5, lane = gt & 31;
    if (node >= n) return;
    const float* row = x + (size_t)node * HF;
    float s = 0.f;
    #pragma unroll
    for (int f = lane; f < HF; f += 32) s += row[f] * w[f];
    #pragma unroll
    for (int o = 16; o > 0; o >>= 1) s += __shfl_down_sync(0xFFFFFFFFu, s, o);
    if (lane == 0) score[node] = tanhf(s * g_winv);
}

// one block per graph; threads = npg; rank-count selection == stable top_k
__global__ void pool_kernel(const float* __restrict__ score, int npg, int k,
                            int* __restrict__ newid, int* __restrict__ perm) {
    __shared__ float s[256];
    int g = blockIdx.x, t = threadIdx.x;
    int node = g * npg + t;
    float my = score[node];
    s[t] = my;
    __syncthreads();
    int rank = 0;
    for (int j = 0; j < npg; j++) {
        float v = s[j];
        rank += (v > my) || (v == my && j < t);
    }
    if (rank < k) {
        newid[node] = g * k + rank;
        perm[g * k + rank] = node;
    } else {
        newid[node] = -1;
    }
}

__global__ void gather_scale_kernel(const float* __restrict__ x, const float* __restrict__ score,
                                    const int* __restrict__ perm, float* __restrict__ nx, int nNew) {
    int i = blockIdx.x * blockDim.x + threadIdx.x;
    if (i >= nNew * HF) return;
    int nn = i >> 8, f = i & 255;
    int old = perm[nn];
    nx[i] = x[(size_t)old * HF + f] * score[old];
}

__global__ void remap_kernel(const int* __restrict__ src, const int* __restrict__ dst,
                             const float* __restrict__ ew, const int* __restrict__ newid,
                             int* __restrict__ nsrc, int* __restrict__ ndst,
                             float* __restrict__ new_ew, int E) {
    int e = blockIdx.x * blockDim.x + threadIdx.x;
    if (e >= E) return;
    int s = newid[src[e]], d = newid[dst[e]];
    float w = ew ? ew[e] : 1.0f;
    bool valid = (s >= 0) && (d >= 0);
    nsrc[e]   = valid ? s : 0;
    ndst[e]   = valid ? d : 0;
    new_ew[e] = valid ? w : 0.f;
}

// ---------------- readout: [max | mean] per graph ----------------
__global__ void readout_kernel(const float* __restrict__ x, int k,
                               float* __restrict__ ro, int accumulate) {
    int g = blockIdx.x, f = threadIdx.x;  // 256 threads
    const float* base = x + (size_t)g * k * HF + f;
    float mx = -3.4e38f, sum = 0.f;
    for (int j = 0; j < k; j++) {
        float v = base[(size_t)j * HF];
        mx = fmaxf(mx, v);
        sum += v;
    }
    float mean = sum / (float)k;
    if (accumulate) {
        ro[g*512 + f]       += mx;
        ro[g*512 + 256 + f] += mean;
    } else {
        ro[g*512 + f]       = mx;
        ro[g*512 + 256 + f] = mean;
    }
}

// ---------------- MLP ----------------
__global__ void lin1_kernel(const float* __restrict__ in, const float* __restrict__ W,
                            const float* __restrict__ b, float* __restrict__ out) {
    int g = blockIdx.x, c = threadIdx.x;  // 256 threads
    __shared__ float row[512];
    for (int i = c; i < 512; i += 256) row[i] = in[g*512 + i];
    __syncthreads();
    float acc = b[c];
    #pragma unroll 8
    for (int kk = 0; kk < 512; kk++) acc += row[kk] * W[kk*256 + c];
    out[g*256 + c] = fmaxf(acc, 0.f);
}
__global__ void lin2_kernel(const float* __restrict__ in, const float* __restrict__ W,
                            const float* __restrict__ b, float* __restrict__ out) {
    int g = blockIdx.x, c = threadIdx.x;  // 128 threads
    __shared__ float row[256];
    for (int i = c; i < 256; i += 128) row[i] = in[g*256 + i];
    __syncthreads();
    float acc = b[c];
    #pragma unroll 8
    for (int kk = 0; kk < 256; kk++) acc += row[kk] * W[kk*128 + c];
    out[g*128 + c] = fmaxf(acc, 0.f);
}
__global__ void lin3_lsm_kernel(const float* __restrict__ in, const float* __restrict__ W,
                                const float* __restrict__ b, float* __restrict__ out) {
    int g = blockIdx.x, lane = threadIdx.x;  // 32 threads
    const float* row = in + g*128;
    float a0 = 0.f, a1 = 0.f;
    #pragma unroll
    for (int kk = lane; kk < 128; kk += 32) {
        float v = row[kk];
        a0 += v * W[kk*2 + 0];
        a1 += v * W[kk*2 + 1];
    }
    #pragma unroll
    for (int o = 16; o > 0; o >>= 1) {
        a0 += __shfl_down_sync(0xFFFFFFFFu, a0, o);
        a1 += __shfl_down_sync(0xFFFFFFFFu, a1, o);
    }
    if (lane == 0) {
        float l0 = a0 + b[0], l1 = a1 + b[1];
        float m = fmaxf(l0, l1);
        float lse = m + logf(expf(l0 - m) + expf(l1 - m));
        out[g*2 + 0] = l0 - lse;
        out[g*2 + 1] = l1 - lse;
    }
}

// ---------------- host driver ----------------
extern "C" void kernel_launch(void* const* d_in, const int* in_sizes, int n_in,
                              void* d_out, int out_size) {
    const float* d_x      = (const float*)d_in[0];
    const int*   d_ei     = (const int*)d_in[1];
    const float* gcn_w0   = (const float*)d_in[3];
    const float* gcn_b0   = (const float*)d_in[4];
    const float* gcn_w1   = (const float*)d_in[5];
    const float* gcn_b1   = (const float*)d_in[6];
    const float* gcn_w2   = (const float*)d_in[7];
    const float* gcn_b2   = (const float*)d_in[8];
    const float* pool_w0  = (const float*)d_in[9];
    const float* pool_w1  = (const float*)d_in[10];
    const float* pool_w2  = (const float*)d_in[11];
    const float* lin1_w   = (const float*)d_in[12];
    const float* lin1_b   = (const float*)d_in[13];
    const float* lin2_w   = (const float*)d_in[14];
    const float* lin2_b   = (const float*)d_in[15];
    const float* lin3_w   = (const float*)d_in[16];
    const float* lin3_b   = (const float*)d_in[17];
    float* out = (float*)d_out;

    const int E = in_sizes[1] / 2;
    const int* d_src = d_ei;
    const int* d_dst = d_ei + E;

    float *p_h, *p_agg, *p_x, *p_dinv, *p_score, *p_ro, *p_h1, *p_h2, *p_cnorm;
    int *p_newid, *p_perm, *p_es0, *p_ed0, *p_es1, *p_ed1, *p_rs, *p_rc, *p_csrc;
    float *p_ew0, *p_ew1;
    cudaGetSymbolAddress((void**)&p_h,    g_h);
    cudaGetSymbolAddress((void**)&p_agg,  g_agg);
    cudaGetSymbolAddress((void**)&p_x,    g_x);
    cudaGetSymbolAddress((void**)&p_dinv, g_dinv);
    cudaGetSymbolAddress((void**)&p_score,g_score);
    cudaGetSymbolAddress((void**)&p_newid,g_newid);
    cudaGetSymbolAddress((void**)&p_perm, g_perm);
    cudaGetSymbolAddress((void**)&p_es0,  g_esrc0);
    cudaGetSymbolAddress((void**)&p_ed0,  g_edst0);
    cudaGetSymbolAddress((void**)&p_ew0,  g_eew0);
    cudaGetSymbolAddress((void**)&p_es1,  g_esrc1);
    cudaGetSymbolAddress((void**)&p_ed1,  g_edst1);
    cudaGetSymbolAddress((void**)&p_ew1,  g_eew1);
    cudaGetSymbolAddress((void**)&p_rs,   g_rs);
    cudaGetSymbolAddress((void**)&p_rc,   g_rc);
    cudaGetSymbolAddress((void**)&p_csrc, g_csrc);
    cudaGetSymbolAddress((void**)&p_cnorm,g_cnorm);
    cudaGetSymbolAddress((void**)&p_ro,   g_ro);
    cudaGetSymbolAddress((void**)&p_h1,   g_h1);
    cudaGetSymbolAddress((void**)&p_h2,   g_h2);

    cudaFuncSetAttribute(agg_fused_kernel,
                         cudaFuncAttributeMaxDynamicSharedMemorySize, 65536);

    // ---------------- level 0 ----------------
    int n = MAXN;                 // 65536 nodes
    {
        int npg = 256;
        gemm_kernel<<<dim3(n / GBM, 256 / GBN), 256>>>(d_x, gcn_w0, p_h, n, 128);
        csr_build_kernel<<<G, 256>>>(d_src, d_dst, nullptr, npg,
                                     p_rs, p_rc, p_csrc, p_cnorm, p_dinv);
        agg_fused_kernel<<<dim3(4, G), 256, npg*64*4>>>(p_h, p_dinv, p_rs, p_rc,
                                                        p_csrc, p_cnorm, gcn_b0, p_agg, npg);
    }

    // pool 0: npg=256 -> k=128
    {
        int npg = 256, k = 128, nNew = G * k;
        wnorm_kernel<<<1, 256>>>(pool_w0);
        score_kernel<<<(n * 32 + 255) / 256, 256>>>(p_agg, pool_w0, p_score, n);
        pool_kernel<<<G, npg>>>(p_score, npg, k, p_newid, p_perm);
        gather_scale_kernel<<<(nNew * HF + 255) / 256, 256>>>(p_agg, p_score, p_perm, p_x, nNew);
        remap_kernel<<<(E + 255) / 256, 256>>>(d_src, d_dst, nullptr, p_newid,
                                               p_es0, p_ed0, p_ew0, E);
        readout_kernel<<<G, 256>>>(p_x, k, p_ro, 0);
        n = nNew;                 // 32768
    }

    // ---------------- level 1 ----------------
    {
        int npg = 128;
        gemm_kernel<<<dim3(n / GBM, 256 / GBN), 256>>>(p_x, gcn_w1, p_h, n, 256);
        csr_build_kernel<<<G, 256>>>(p_es0, p_ed0, p_ew0, npg,
                                     p_rs, p_rc, p_csrc, p_cnorm, p_dinv);
        agg_fused_kernel<<<dim3(4, G), 256, npg*64*4>>>(p_h, p_dinv, p_rs, p_rc,
                                                        p_csrc, p_cnorm, gcn_b1, p_agg, npg);
    }
    {
        int npg = 128, k = 64, nNew = G * k;
        wnorm_kernel<<<1, 256>>>(pool_w1);
        score_kernel<<<(n * 32 + 255) / 256, 256>>>(p_agg, pool_w1, p_score, n);
        pool_kernel<<<G, npg>>>(p_score, npg, k, p_newid, p_perm);
        gather_scale_kernel<<<(nNew * HF + 255) / 256, 256>>>(p_agg, p_score, p_perm, p_x, nNew);
        remap_kernel<<<(E + 255) / 256, 256>>>(p_es0, p_ed0, p_ew0, p_newid,
                                               p_es1, p_ed1, p_ew1, E);
        readout_kernel<<<G, 256>>>(p_x, k, p_ro, 1);
        n = nNew;                 // 16384
    }

    // ---------------- level 2 ----------------
    {
        int npg = 64;
        gemm_kernel<<<dim3(n / GBM, 256 / GBN), 256>>>(p_x, gcn_w2, p_h, n, 256);
        csr_build_kernel<<<G, 256>>>(p_es1, p_ed1, p_ew1, npg,
                                     p_rs, p_rc, p_csrc, p_cnorm, p_dinv);
        agg_fused_kernel<<<dim3(4, G), 256, npg*64*4>>>(p_h, p_dinv, p_rs, p_rc,
                                                        p_csrc, p_cnorm, gcn_b2, p_agg, npg);
    }
    {
        int npg = 64, k = 32, nNew = G * k;
        wnorm_kernel<<<1, 256>>>(pool_w2);
        score_kernel<<<(n * 32 + 255) / 256, 256>>>(p_agg, pool_w2, p_score, n);
        pool_kernel<<<G, npg>>>(p_score, npg, k, p_newid, p_perm);
        gather_scale_kernel<<<(nNew * HF + 255) / 256, 256>>>(p_agg, p_score, p_perm, p_x, nNew);
        readout_kernel<<<G, 256>>>(p_x, k, p_ro, 1);
    }

    // ---------------- MLP head ----------------
    lin1_kernel<<<G, 256>>>(p_ro, lin1_w, lin1_b, p_h1);
    lin2_kernel<<<G, 128>>>(p_h1, lin2_w, lin2_b, p_h2);
    lin3_lsm_kernel<<<G, 32>>>(p_h2, lin3_w, lin3_b, out);
}